// round 1
// baseline (speedup 1.0000x reference)
#include <cuda_runtime.h>

// Problem shapes (fixed by the dataset)
#define BB 4
#define CC 256
#define CO 32
#define NN 4096   // H*W = 64*64

// Scratch (allocation-free rule: __device__ globals)
__device__ float g_q[BB * CO * NN];                 // 2 MB
__device__ float g_k[BB * CO * NN];                 // 2 MB
__device__ float g_v[(size_t)BB * CC * NN];         // 16 MB

// ---------------------------------------------------------------------------
// Kernel 1: q/k projection.  q[b,o,n] = sum_c Wq[o,c] x[b,c,n] + bq[o]
// Block: 256 threads, handles one batch b and 128 n-columns, all 32 rows,
// for BOTH q and k.  K chunked by 32.
// ---------------------------------------------------------------------------
__global__ __launch_bounds__(256) void qk_proj(
    const float* __restrict__ x,
    const float* __restrict__ Wq, const float* __restrict__ bq,
    const float* __restrict__ Wk, const float* __restrict__ bk)
{
    const int b  = blockIdx.y;
    const int n0 = blockIdx.x * 128;

    __shared__ float xs[32][128];
    __shared__ float wqs[32][32];   // [c_local][o]
    __shared__ float wks[32][32];

    const int tid = threadIdx.x;
    const int nl  = tid & 127;      // 0..127 column
    const int oh  = tid >> 7;       // 0/1: which half of the 32 rows

    float accq[16], acck[16];
    #pragma unroll
    for (int r = 0; r < 16; r++) { accq[r] = 0.f; acck[r] = 0.f; }

    const float* xb = x + (size_t)b * CC * NN;

    for (int c0 = 0; c0 < CC; c0 += 32) {
        for (int i = tid; i < 32 * 128; i += 256) {
            int cc = i >> 7, nn = i & 127;
            xs[cc][nn] = xb[(size_t)(c0 + cc) * NN + n0 + nn];
        }
        for (int i = tid; i < 32 * 32; i += 256) {
            int o = i >> 5, cc = i & 31;
            wqs[cc][o] = Wq[o * CC + c0 + cc];
            wks[cc][o] = Wk[o * CC + c0 + cc];
        }
        __syncthreads();
        #pragma unroll
        for (int kk = 0; kk < 32; kk++) {
            float xv = xs[kk][nl];
            #pragma unroll
            for (int r = 0; r < 16; r++) {
                accq[r] += wqs[kk][oh * 16 + r] * xv;
                acck[r] += wks[kk][oh * 16 + r] * xv;
            }
        }
        __syncthreads();
    }
    #pragma unroll
    for (int r = 0; r < 16; r++) {
        int o = oh * 16 + r;
        g_q[((size_t)b * CO + o) * NN + n0 + nl] = accq[r] + bq[o];
        g_k[((size_t)b * CO + o) * NN + n0 + nl] = acck[r] + bk[o];
    }
}

// ---------------------------------------------------------------------------
// Kernel 2: v projection.  v[b,c,n] = sum_k Wv[c,k] x[b,k,n] + bv[c]
// Classic 128x128 tile SGEMM, BK=16, 256 threads, 8x8 micro-tile.
// ---------------------------------------------------------------------------
__global__ __launch_bounds__(256) void v_proj(
    const float* __restrict__ x,
    const float* __restrict__ Wv, const float* __restrict__ bv)
{
    const int b  = blockIdx.z;
    const int c0 = blockIdx.y * 128;   // output channel rows
    const int n0 = blockIdx.x * 128;   // pixel columns

    __shared__ float As[16][128];      // transposed A: As[k][c]
    __shared__ float Bs[16][128];      // Bs[k][n]

    const int tid = threadIdx.x;
    const int tx = tid & 15, ty = tid >> 4;

    float acc[8][8];
    #pragma unroll
    for (int r = 0; r < 8; r++)
        #pragma unroll
        for (int s = 0; s < 8; s++) acc[r][s] = 0.f;

    const float* xb = x + (size_t)b * CC * NN;

    for (int k0 = 0; k0 < CC; k0 += 16) {
        #pragma unroll
        for (int it = 0; it < 2; it++) {
            int idx = tid + it * 256;          // 0..511 float4 slots
            int row = idx >> 2;                // 0..127
            int c4  = (idx & 3) * 4;
            float4 v4 = *reinterpret_cast<const float4*>(&Wv[(c0 + row) * CC + k0 + c4]);
            As[c4 + 0][row] = v4.x; As[c4 + 1][row] = v4.y;
            As[c4 + 2][row] = v4.z; As[c4 + 3][row] = v4.w;
        }
        #pragma unroll
        for (int it = 0; it < 2; it++) {
            int idx  = tid + it * 256;
            int krow = idx >> 5;               // 0..15
            int nc4  = (idx & 31) * 4;
            *reinterpret_cast<float4*>(&Bs[krow][nc4]) =
                *reinterpret_cast<const float4*>(&xb[(size_t)(k0 + krow) * NN + n0 + nc4]);
        }
        __syncthreads();
        #pragma unroll
        for (int kk = 0; kk < 16; kk++) {
            float4 a0 = *reinterpret_cast<const float4*>(&As[kk][ty * 8]);
            float4 a1 = *reinterpret_cast<const float4*>(&As[kk][ty * 8 + 4]);
            float4 b0 = *reinterpret_cast<const float4*>(&Bs[kk][tx * 8]);
            float4 b1 = *reinterpret_cast<const float4*>(&Bs[kk][tx * 8 + 4]);
            float ra[8] = {a0.x, a0.y, a0.z, a0.w, a1.x, a1.y, a1.z, a1.w};
            float rb[8] = {b0.x, b0.y, b0.z, b0.w, b1.x, b1.y, b1.z, b1.w};
            #pragma unroll
            for (int r = 0; r < 8; r++)
                #pragma unroll
                for (int s = 0; s < 8; s++) acc[r][s] += ra[r] * rb[s];
        }
        __syncthreads();
    }

    #pragma unroll
    for (int r = 0; r < 8; r++) {
        int c = c0 + ty * 8 + r;
        float bias = bv[c];
        #pragma unroll
        for (int s = 0; s < 8; s += 4) {
            float4 o;
            o.x = acc[r][s + 0] + bias; o.y = acc[r][s + 1] + bias;
            o.z = acc[r][s + 2] + bias; o.w = acc[r][s + 3] + bias;
            *reinterpret_cast<float4*>(&g_v[((size_t)b * CC + c) * NN + n0 + tx * 8 + s]) = o;
        }
    }
}

// ---------------------------------------------------------------------------
// Kernel 3: raw scores.  scores[b,n,m] = sum_{c<32} k[b,c,n] * q[b,c,m]
// 128(n) x 128(m) tile, K=32 in one shot.  Writes raw scores into the attn
// region of d_out (normalized in place by the softmax kernel).
// ---------------------------------------------------------------------------
__global__ __launch_bounds__(256) void scores_kernel(float* __restrict__ attn)
{
    const int b  = blockIdx.z;
    const int m0 = blockIdx.x * 128;
    const int n0 = blockIdx.y * 128;

    __shared__ float ks[CO][128];
    __shared__ float qs[CO][128];

    const int tid = threadIdx.x;
    const float* kb = g_k + (size_t)b * CO * NN;
    const float* qb = g_q + (size_t)b * CO * NN;

    #pragma unroll
    for (int it = 0; it < 4; it++) {
        int idx = tid + it * 256;          // 0..1023 float4 slots
        int row = idx >> 5;                // 0..31 (channel)
        int c4  = (idx & 31) * 4;
        *reinterpret_cast<float4*>(&ks[row][c4]) =
            *reinterpret_cast<const float4*>(&kb[(size_t)row * NN + n0 + c4]);
        *reinterpret_cast<float4*>(&qs[row][c4]) =
            *reinterpret_cast<const float4*>(&qb[(size_t)row * NN + m0 + c4]);
    }
    __syncthreads();

    const int tx = tid & 15, ty = tid >> 4;
    float acc[8][8];
    #pragma unroll
    for (int r = 0; r < 8; r++)
        #pragma unroll
        for (int s = 0; s < 8; s++) acc[r][s] = 0.f;

    #pragma unroll
    for (int c = 0; c < CO; c++) {
        float4 a0 = *reinterpret_cast<const float4*>(&ks[c][ty * 8]);
        float4 a1 = *reinterpret_cast<const float4*>(&ks[c][ty * 8 + 4]);
        float4 b0 = *reinterpret_cast<const float4*>(&qs[c][tx * 8]);
        float4 b1 = *reinterpret_cast<const float4*>(&qs[c][tx * 8 + 4]);
        float ra[8] = {a0.x, a0.y, a0.z, a0.w, a1.x, a1.y, a1.z, a1.w};
        float rb[8] = {b0.x, b0.y, b0.z, b0.w, b1.x, b1.y, b1.z, b1.w};
        #pragma unroll
        for (int r = 0; r < 8; r++)
            #pragma unroll
            for (int s = 0; s < 8; s++) acc[r][s] += ra[r] * rb[s];
    }

    float* ap = attn + (size_t)b * NN * NN;
    #pragma unroll
    for (int r = 0; r < 8; r++) {
        size_t n = (size_t)(n0 + ty * 8 + r);
        #pragma unroll
        for (int s = 0; s < 8; s += 4) {
            float4 o;
            o.x = acc[r][s + 0]; o.y = acc[r][s + 1];
            o.z = acc[r][s + 2]; o.w = acc[r][s + 3];
            *reinterpret_cast<float4*>(&ap[n * NN + m0 + tx * 8 + s]) = o;
        }
    }
}

// ---------------------------------------------------------------------------
// Kernel 4: softmax over the last axis (m), in place.  One block per row.
// ---------------------------------------------------------------------------
__global__ __launch_bounds__(256) void softmax_rows(float* __restrict__ attn)
{
    __shared__ float buf[NN];      // 16 KB row buffer
    __shared__ float red[32];

    const size_t row = blockIdx.x;
    float* p = attn + row * NN;
    const int tid  = threadIdx.x;
    const int lane = tid & 31, wid = tid >> 5;

    float lmax = -1e30f;
    for (int i = tid; i < NN; i += 256) {
        float v = p[i];
        buf[i] = v;
        lmax = fmaxf(lmax, v);
    }
    #pragma unroll
    for (int o = 16; o; o >>= 1) lmax = fmaxf(lmax, __shfl_xor_sync(0xffffffffu, lmax, o));
    if (lane == 0) red[wid] = lmax;
    __syncthreads();
    if (tid < 32) {
        float v = (tid < 8) ? red[tid] : -1e30f;
        #pragma unroll
        for (int o = 4; o; o >>= 1) v = fmaxf(v, __shfl_xor_sync(0xffffffffu, v, o));
        if (tid == 0) red[0] = v;
    }
    __syncthreads();
    const float rmax = red[0];
    __syncthreads();   // red[0] consumed by all before reuse below

    float lsum = 0.f;
    for (int i = tid; i < NN; i += 256) {
        float e = __expf(buf[i] - rmax);
        buf[i] = e;
        lsum += e;
    }
    #pragma unroll
    for (int o = 16; o; o >>= 1) lsum += __shfl_xor_sync(0xffffffffu, lsum, o);
    if (lane == 0) red[wid] = lsum;
    __syncthreads();
    if (tid < 32) {
        float v = (tid < 8) ? red[tid] : 0.f;
        #pragma unroll
        for (int o = 4; o; o >>= 1) v += __shfl_xor_sync(0xffffffffu, v, o);
        if (tid == 0) red[0] = v;
    }
    __syncthreads();
    const float inv = 1.0f / red[0];

    for (int i = tid; i < NN; i += 256)
        p[i] = buf[i] * inv;
}

// ---------------------------------------------------------------------------
// Kernel 5: out[b,c,m] = gamma * sum_n v[b,c,n] * attn[b,n,m] + x[b,c,m]
// 128x128 tile SGEMM over K=N=4096, BK=16.
// ---------------------------------------------------------------------------
__global__ __launch_bounds__(256) void out_gemm(
    const float* __restrict__ attn,
    const float* __restrict__ x,
    const float* __restrict__ gamma,
    float* __restrict__ out)
{
    const int b  = blockIdx.z;
    const int c0 = blockIdx.y * 128;
    const int m0 = blockIdx.x * 128;

    __shared__ float As[16][128];      // As[k][c]  (v transposed)
    __shared__ float Bs[16][128];      // Bs[k][m]  (attn)

    const float* vb = g_v + (size_t)b * CC * NN;
    const float* ab = attn + (size_t)b * NN * NN;

    const int tid = threadIdx.x;
    const int tx = tid & 15, ty = tid >> 4;

    float acc[8][8];
    #pragma unroll
    for (int r = 0; r < 8; r++)
        #pragma unroll
        for (int s = 0; s < 8; s++) acc[r][s] = 0.f;

    for (int k0 = 0; k0 < NN; k0 += 16) {
        #pragma unroll
        for (int it = 0; it < 2; it++) {
            int idx = tid + it * 256;
            int row = idx >> 2;                // c row 0..127
            int c4  = (idx & 3) * 4;           // k offset
            float4 v4 = *reinterpret_cast<const float4*>(&vb[(size_t)(c0 + row) * NN + k0 + c4]);
            As[c4 + 0][row] = v4.x; As[c4 + 1][row] = v4.y;
            As[c4 + 2][row] = v4.z; As[c4 + 3][row] = v4.w;
        }
        #pragma unroll
        for (int it = 0; it < 2; it++) {
            int idx  = tid + it * 256;
            int krow = idx >> 5;
            int nc4  = (idx & 31) * 4;
            *reinterpret_cast<float4*>(&Bs[krow][nc4]) =
                *reinterpret_cast<const float4*>(&ab[(size_t)(k0 + krow) * NN + m0 + nc4]);
        }
        __syncthreads();
        #pragma unroll
        for (int kk = 0; kk < 16; kk++) {
            float4 a0 = *reinterpret_cast<const float4*>(&As[kk][ty * 8]);
            float4 a1 = *reinterpret_cast<const float4*>(&As[kk][ty * 8 + 4]);
            float4 b0 = *reinterpret_cast<const float4*>(&Bs[kk][tx * 8]);
            float4 b1 = *reinterpret_cast<const float4*>(&Bs[kk][tx * 8 + 4]);
            float ra[8] = {a0.x, a0.y, a0.z, a0.w, a1.x, a1.y, a1.z, a1.w};
            float rb[8] = {b0.x, b0.y, b0.z, b0.w, b1.x, b1.y, b1.z, b1.w};
            #pragma unroll
            for (int r = 0; r < 8; r++)
                #pragma unroll
                for (int s = 0; s < 8; s++) acc[r][s] += ra[r] * rb[s];
        }
        __syncthreads();
    }

    const float g = __ldg(gamma);
    const float* xb = x + (size_t)b * CC * NN;

    #pragma unroll
    for (int r = 0; r < 8; r++) {
        int c = c0 + ty * 8 + r;
        #pragma unroll
        for (int s = 0; s < 8; s += 4) {
            size_t base = (size_t)c * NN + m0 + tx * 8 + s;
            float4 xr = *reinterpret_cast<const float4*>(&xb[base]);
            float4 o;
            o.x = g * acc[r][s + 0] + xr.x;
            o.y = g * acc[r][s + 1] + xr.y;
            o.z = g * acc[r][s + 2] + xr.z;
            o.w = g * acc[r][s + 3] + xr.w;
            *reinterpret_cast<float4*>(&out[(size_t)b * CC * NN + base]) = o;
        }
    }
}

// ---------------------------------------------------------------------------
extern "C" void kernel_launch(void* const* d_in, const int* in_sizes, int n_in,
                              void* d_out, int out_size)
{
    (void)in_sizes; (void)n_in; (void)out_size;

    const float* x     = (const float*)d_in[0];
    const float* Wq    = (const float*)d_in[1];
    const float* bq    = (const float*)d_in[2];
    const float* Wk    = (const float*)d_in[3];
    const float* bk    = (const float*)d_in[4];
    const float* Wv    = (const float*)d_in[5];
    const float* bv    = (const float*)d_in[6];
    const float* gamma = (const float*)d_in[7];

    float* out  = (float*)d_out;                       // (B, C, H, W)
    float* attn = out + (size_t)BB * CC * NN;          // (B, N, N)

    qk_proj      <<<dim3(NN / 128, BB), 256>>>(x, Wq, bq, Wk, bk);
    v_proj       <<<dim3(NN / 128, CC / 128, BB), 256>>>(x, Wv, bv);
    scores_kernel<<<dim3(NN / 128, NN / 128, BB), 256>>>(attn);
    softmax_rows <<<BB * NN, 256>>>(attn);
    out_gemm     <<<dim3(NN / 128, CC / 128, BB), 256>>>(attn, x, gamma, out);
}

// round 2
// speedup vs baseline: 2.1572x; 2.1572x over previous
#include <cuda_runtime.h>
#include <cstdint>

// Problem shapes (fixed by the dataset)
#define BB 4
#define CC 256
#define CO 32
#define NN 4096   // H*W = 64*64

// Scratch (allocation-free rule: __device__ globals)
__device__ float g_q[BB * CO * NN];                 // 2 MB
__device__ float g_k[BB * CO * NN];                 // 2 MB
__device__ float g_v[(size_t)BB * CC * NN];         // 16 MB

// ---------------------------------------------------------------------------
// tf32 helpers
// ---------------------------------------------------------------------------
__device__ __forceinline__ float to_tf32(float x) {
    uint32_t u;
    asm("cvt.rna.tf32.f32 %0, %1;" : "=r"(u) : "f"(x));
    return __uint_as_float(u);
}

__device__ __forceinline__ void mma_tf32_16x8x8(
    float c[4], const uint32_t a[4], const uint32_t b[2])
{
    asm volatile(
        "mma.sync.aligned.m16n8k8.row.col.f32.tf32.tf32.f32 "
        "{%0,%1,%2,%3}, {%4,%5,%6,%7}, {%8,%9}, {%0,%1,%2,%3};"
        : "+f"(c[0]), "+f"(c[1]), "+f"(c[2]), "+f"(c[3])
        : "r"(a[0]), "r"(a[1]), "r"(a[2]), "r"(a[3]),
          "r"(b[0]), "r"(b[1]));
}

// ---------------------------------------------------------------------------
// Kernel 1: q/k projection.  q[b,o,n] = sum_c Wq[o,c] x[b,c,n] + bq[o]
// ---------------------------------------------------------------------------
__global__ __launch_bounds__(256) void qk_proj(
    const float* __restrict__ x,
    const float* __restrict__ Wq, const float* __restrict__ bq,
    const float* __restrict__ Wk, const float* __restrict__ bk)
{
    const int b  = blockIdx.y;
    const int n0 = blockIdx.x * 128;

    __shared__ float xs[32][128];
    __shared__ float wqs[32][32];   // [c_local][o]
    __shared__ float wks[32][32];

    const int tid = threadIdx.x;
    const int nl  = tid & 127;      // 0..127 column
    const int oh  = tid >> 7;       // 0/1: which half of the 32 rows

    float accq[16], acck[16];
    #pragma unroll
    for (int r = 0; r < 16; r++) { accq[r] = 0.f; acck[r] = 0.f; }

    const float* xb = x + (size_t)b * CC * NN;

    for (int c0 = 0; c0 < CC; c0 += 32) {
        for (int i = tid; i < 32 * 128; i += 256) {
            int cc = i >> 7, nn = i & 127;
            xs[cc][nn] = xb[(size_t)(c0 + cc) * NN + n0 + nn];
        }
        for (int i = tid; i < 32 * 32; i += 256) {
            int o = i >> 5, cc = i & 31;
            wqs[cc][o] = Wq[o * CC + c0 + cc];
            wks[cc][o] = Wk[o * CC + c0 + cc];
        }
        __syncthreads();
        #pragma unroll
        for (int kk = 0; kk < 32; kk++) {
            float xv = xs[kk][nl];
            #pragma unroll
            for (int r = 0; r < 16; r++) {
                accq[r] += wqs[kk][oh * 16 + r] * xv;
                acck[r] += wks[kk][oh * 16 + r] * xv;
            }
        }
        __syncthreads();
    }
    #pragma unroll
    for (int r = 0; r < 16; r++) {
        int o = oh * 16 + r;
        g_q[((size_t)b * CO + o) * NN + n0 + nl] = accq[r] + bq[o];
        g_k[((size_t)b * CO + o) * NN + n0 + nl] = acck[r] + bk[o];
    }
}

// ---------------------------------------------------------------------------
// Kernel 2: v projection (fp32 SIMT; only 2.1 GF).
// ---------------------------------------------------------------------------
__global__ __launch_bounds__(256) void v_proj(
    const float* __restrict__ x,
    const float* __restrict__ Wv, const float* __restrict__ bv)
{
    const int b  = blockIdx.z;
    const int c0 = blockIdx.y * 128;
    const int n0 = blockIdx.x * 128;

    __shared__ float As[16][128];
    __shared__ float Bs[16][128];

    const int tid = threadIdx.x;
    const int tx = tid & 15, ty = tid >> 4;

    float acc[8][8];
    #pragma unroll
    for (int r = 0; r < 8; r++)
        #pragma unroll
        for (int s = 0; s < 8; s++) acc[r][s] = 0.f;

    const float* xb = x + (size_t)b * CC * NN;

    for (int k0 = 0; k0 < CC; k0 += 16) {
        #pragma unroll
        for (int it = 0; it < 2; it++) {
            int idx = tid + it * 256;
            int row = idx >> 2;
            int c4  = (idx & 3) * 4;
            float4 v4 = *reinterpret_cast<const float4*>(&Wv[(c0 + row) * CC + k0 + c4]);
            As[c4 + 0][row] = v4.x; As[c4 + 1][row] = v4.y;
            As[c4 + 2][row] = v4.z; As[c4 + 3][row] = v4.w;
        }
        #pragma unroll
        for (int it = 0; it < 2; it++) {
            int idx  = tid + it * 256;
            int krow = idx >> 5;
            int nc4  = (idx & 31) * 4;
            *reinterpret_cast<float4*>(&Bs[krow][nc4]) =
                *reinterpret_cast<const float4*>(&xb[(size_t)(k0 + krow) * NN + n0 + nc4]);
        }
        __syncthreads();
        #pragma unroll
        for (int kk = 0; kk < 16; kk++) {
            float4 a0 = *reinterpret_cast<const float4*>(&As[kk][ty * 8]);
            float4 a1 = *reinterpret_cast<const float4*>(&As[kk][ty * 8 + 4]);
            float4 b0 = *reinterpret_cast<const float4*>(&Bs[kk][tx * 8]);
            float4 b1 = *reinterpret_cast<const float4*>(&Bs[kk][tx * 8 + 4]);
            float ra[8] = {a0.x, a0.y, a0.z, a0.w, a1.x, a1.y, a1.z, a1.w};
            float rb[8] = {b0.x, b0.y, b0.z, b0.w, b1.x, b1.y, b1.z, b1.w};
            #pragma unroll
            for (int r = 0; r < 8; r++)
                #pragma unroll
                for (int s = 0; s < 8; s++) acc[r][s] += ra[r] * rb[s];
        }
        __syncthreads();
    }

    #pragma unroll
    for (int r = 0; r < 8; r++) {
        int c = c0 + ty * 8 + r;
        float bias = bv[c];
        #pragma unroll
        for (int s = 0; s < 8; s += 4) {
            float4 o;
            o.x = acc[r][s + 0] + bias; o.y = acc[r][s + 1] + bias;
            o.z = acc[r][s + 2] + bias; o.w = acc[r][s + 3] + bias;
            *reinterpret_cast<float4*>(&g_v[((size_t)b * CC + c) * NN + n0 + tx * 8 + s]) = o;
        }
    }
}

// ---------------------------------------------------------------------------
// Kernel 3: raw scores, full fp32 (precision-critical: feeds softmax).
// ---------------------------------------------------------------------------
__global__ __launch_bounds__(256) void scores_kernel(float* __restrict__ attn)
{
    const int b  = blockIdx.z;
    const int m0 = blockIdx.x * 128;
    const int n0 = blockIdx.y * 128;

    __shared__ float ks[CO][128];
    __shared__ float qs[CO][128];

    const int tid = threadIdx.x;
    const float* kb = g_k + (size_t)b * CO * NN;
    const float* qb = g_q + (size_t)b * CO * NN;

    #pragma unroll
    for (int it = 0; it < 4; it++) {
        int idx = tid + it * 256;
        int row = idx >> 5;
        int c4  = (idx & 31) * 4;
        *reinterpret_cast<float4*>(&ks[row][c4]) =
            *reinterpret_cast<const float4*>(&kb[(size_t)row * NN + n0 + c4]);
        *reinterpret_cast<float4*>(&qs[row][c4]) =
            *reinterpret_cast<const float4*>(&qb[(size_t)row * NN + m0 + c4]);
    }
    __syncthreads();

    const int tx = tid & 15, ty = tid >> 4;
    float acc[8][8];
    #pragma unroll
    for (int r = 0; r < 8; r++)
        #pragma unroll
        for (int s = 0; s < 8; s++) acc[r][s] = 0.f;

    #pragma unroll
    for (int c = 0; c < CO; c++) {
        float4 a0 = *reinterpret_cast<const float4*>(&ks[c][ty * 8]);
        float4 a1 = *reinterpret_cast<const float4*>(&ks[c][ty * 8 + 4]);
        float4 b0 = *reinterpret_cast<const float4*>(&qs[c][tx * 8]);
        float4 b1 = *reinterpret_cast<const float4*>(&qs[c][tx * 8 + 4]);
        float ra[8] = {a0.x, a0.y, a0.z, a0.w, a1.x, a1.y, a1.z, a1.w};
        float rb[8] = {b0.x, b0.y, b0.z, b0.w, b1.x, b1.y, b1.z, b1.w};
        #pragma unroll
        for (int r = 0; r < 8; r++)
            #pragma unroll
            for (int s = 0; s < 8; s++) acc[r][s] += ra[r] * rb[s];
    }

    float* ap = attn + (size_t)b * NN * NN;
    #pragma unroll
    for (int r = 0; r < 8; r++) {
        size_t n = (size_t)(n0 + ty * 8 + r);
        #pragma unroll
        for (int s = 0; s < 8; s += 4) {
            float4 o;
            o.x = acc[r][s + 0]; o.y = acc[r][s + 1];
            o.z = acc[r][s + 2]; o.w = acc[r][s + 3];
            *reinterpret_cast<float4*>(&ap[n * NN + m0 + tx * 8 + s]) = o;
        }
    }
}

// ---------------------------------------------------------------------------
// Kernel 4: softmax over the last axis (m), in place.  One block per row,
// 512 threads to shorten the latency-bound phases.
// ---------------------------------------------------------------------------
__global__ __launch_bounds__(512) void softmax_rows(float* __restrict__ attn)
{
    __shared__ float buf[NN];      // 16 KB row buffer
    __shared__ float red[32];

    const size_t row = blockIdx.x;
    float* p = attn + row * NN;
    const int tid  = threadIdx.x;
    const int lane = tid & 31, wid = tid >> 5;   // 16 warps

    float lmax = -1e30f;
    for (int i = tid; i < NN; i += 512) {
        float v = p[i];
        buf[i] = v;
        lmax = fmaxf(lmax, v);
    }
    #pragma unroll
    for (int o = 16; o; o >>= 1) lmax = fmaxf(lmax, __shfl_xor_sync(0xffffffffu, lmax, o));
    if (lane == 0) red[wid] = lmax;
    __syncthreads();
    if (tid < 32) {
        float v = (tid < 16) ? red[tid] : -1e30f;
        #pragma unroll
        for (int o = 8; o; o >>= 1) v = fmaxf(v, __shfl_xor_sync(0xffffffffu, v, o));
        if (tid == 0) red[0] = v;
    }
    __syncthreads();
    const float rmax = red[0];
    __syncthreads();

    float lsum = 0.f;
    for (int i = tid; i < NN; i += 512) {
        float e = __expf(buf[i] - rmax);
        buf[i] = e;
        lsum += e;
    }
    #pragma unroll
    for (int o = 16; o; o >>= 1) lsum += __shfl_xor_sync(0xffffffffu, lsum, o);
    if (lane == 0) red[wid] = lsum;
    __syncthreads();
    if (tid < 32) {
        float v = (tid < 16) ? red[tid] : 0.f;
        #pragma unroll
        for (int o = 8; o; o >>= 1) v += __shfl_xor_sync(0xffffffffu, v, o);
        if (tid == 0) red[0] = v;
    }
    __syncthreads();
    const float inv = 1.0f / red[0];

    for (int i = tid; i < NN; i += 512)
        p[i] = buf[i] * inv;
}

// ---------------------------------------------------------------------------
// Kernel 5 (tensor cores): out[b,c,m] = gamma * sum_n v[b,c,n]*attn[b,n,m] + x
// mma.sync m16n8k8 tf32.  Block tile 128(c) x 128(m), BK=32(n).
// 8 warps as 2(c) x 4(m); warp tile 64x32.
// As[c][k] pitch 36 (conflict-free fragment loads);
// Bs[k][m] pitch 132 (natural orientation, conflict-free stores, <=2-way loads).
// ---------------------------------------------------------------------------
__global__ __launch_bounds__(256) void out_gemm_tf32(
    const float* __restrict__ attn,
    const float* __restrict__ x,
    const float* __restrict__ gamma,
    float* __restrict__ out)
{
    const int b  = blockIdx.z;
    const int c0 = blockIdx.y * 128;
    const int m0 = blockIdx.x * 128;

    __shared__ float As[128][36];   // v tile, [c][k]
    __shared__ float Bs[32][132];   // attn tile, [k][m]

    const float* vb = g_v + (size_t)b * CC * NN;
    const float* ab = attn + (size_t)b * NN * NN;

    const int tid  = threadIdx.x;
    const int lane = tid & 31;
    const int w    = tid >> 5;
    const int wc   = w >> 2;        // 0..1  (c dim)
    const int wm   = w & 3;         // 0..3  (m dim)

    float acc[4][4][4];
    #pragma unroll
    for (int mi = 0; mi < 4; mi++)
        #pragma unroll
        for (int ni = 0; ni < 4; ni++)
            #pragma unroll
            for (int r = 0; r < 4; r++) acc[mi][ni][r] = 0.f;

    const int lq = lane >> 2;   // 0..7
    const int lr = lane & 3;    // 0..3

    for (int k0 = 0; k0 < NN; k0 += 32) {
        // Load A (v) tile: 128 rows x 32 k, float4, cvt to tf32
        #pragma unroll
        for (int j = 0; j < 4; j++) {
            int idx = tid + j * 256;            // 0..1023
            int row = idx >> 3;                 // 0..127
            int c4  = (idx & 7) * 4;            // 0..28
            float4 v4 = *reinterpret_cast<const float4*>(
                &vb[(size_t)(c0 + row) * NN + k0 + c4]);
            As[row][c4 + 0] = to_tf32(v4.x);
            As[row][c4 + 1] = to_tf32(v4.y);
            As[row][c4 + 2] = to_tf32(v4.z);
            As[row][c4 + 3] = to_tf32(v4.w);
        }
        // Load B (attn) tile: 32 k-rows x 128 m, float4, cvt to tf32
        #pragma unroll
        for (int j = 0; j < 4; j++) {
            int idx = tid + j * 256;            // 0..1023
            int kr  = idx >> 5;                 // 0..31
            int m4  = (idx & 31) * 4;           // 0..124
            float4 v4 = *reinterpret_cast<const float4*>(
                &ab[(size_t)(k0 + kr) * NN + m0 + m4]);
            Bs[kr][m4 + 0] = to_tf32(v4.x);
            Bs[kr][m4 + 1] = to_tf32(v4.y);
            Bs[kr][m4 + 2] = to_tf32(v4.z);
            Bs[kr][m4 + 3] = to_tf32(v4.w);
        }
        __syncthreads();

        #pragma unroll
        for (int kk = 0; kk < 32; kk += 8) {
            uint32_t af[4][4];
            #pragma unroll
            for (int mi = 0; mi < 4; mi++) {
                int r = wc * 64 + mi * 16 + lq;
                af[mi][0] = __float_as_uint(As[r    ][kk + lr    ]);
                af[mi][1] = __float_as_uint(As[r + 8][kk + lr    ]);
                af[mi][2] = __float_as_uint(As[r    ][kk + lr + 4]);
                af[mi][3] = __float_as_uint(As[r + 8][kk + lr + 4]);
            }
            uint32_t bf[4][2];
            #pragma unroll
            for (int ni = 0; ni < 4; ni++) {
                int m = wm * 32 + ni * 8 + lq;
                bf[ni][0] = __float_as_uint(Bs[kk + lr    ][m]);
                bf[ni][1] = __float_as_uint(Bs[kk + lr + 4][m]);
            }
            #pragma unroll
            for (int mi = 0; mi < 4; mi++)
                #pragma unroll
                for (int ni = 0; ni < 4; ni++)
                    mma_tf32_16x8x8(acc[mi][ni], af[mi], bf[ni]);
        }
        __syncthreads();
    }

    // Epilogue: out = gamma * acc + x
    const float g = __ldg(gamma);
    const float* xb = x + (size_t)b * CC * NN;
    float* ob = out + (size_t)b * CC * NN;

    #pragma unroll
    for (int mi = 0; mi < 4; mi++) {
        #pragma unroll
        for (int ni = 0; ni < 4; ni++) {
            int c = c0 + wc * 64 + mi * 16 + lq;
            int m = m0 + wm * 32 + ni * 8 + lr * 2;
            {
                size_t off = (size_t)c * NN + m;
                float2 xr = *reinterpret_cast<const float2*>(&xb[off]);
                float2 o;
                o.x = g * acc[mi][ni][0] + xr.x;
                o.y = g * acc[mi][ni][1] + xr.y;
                *reinterpret_cast<float2*>(&ob[off]) = o;
            }
            {
                size_t off = (size_t)(c + 8) * NN + m;
                float2 xr = *reinterpret_cast<const float2*>(&xb[off]);
                float2 o;
                o.x = g * acc[mi][ni][2] + xr.x;
                o.y = g * acc[mi][ni][3] + xr.y;
                *reinterpret_cast<float2*>(&ob[off]) = o;
            }
        }
    }
}

// ---------------------------------------------------------------------------
extern "C" void kernel_launch(void* const* d_in, const int* in_sizes, int n_in,
                              void* d_out, int out_size)
{
    (void)in_sizes; (void)n_in; (void)out_size;

    const float* x     = (const float*)d_in[0];
    const float* Wq    = (const float*)d_in[1];
    const float* bq    = (const float*)d_in[2];
    const float* Wk    = (const float*)d_in[3];
    const float* bk    = (const float*)d_in[4];
    const float* Wv    = (const float*)d_in[5];
    const float* bv    = (const float*)d_in[6];
    const float* gamma = (const float*)d_in[7];

    float* out  = (float*)d_out;                       // (B, C, H, W)
    float* attn = out + (size_t)BB * CC * NN;          // (B, N, N)

    qk_proj      <<<dim3(NN / 128, BB), 256>>>(x, Wq, bq, Wk, bk);
    v_proj       <<<dim3(NN / 128, CC / 128, BB), 256>>>(x, Wv, bv);
    scores_kernel<<<dim3(NN / 128, NN / 128, BB), 256>>>(attn);
    softmax_rows <<<BB * NN, 512>>>(attn);
    out_gemm_tf32<<<dim3(NN / 128, CC / 128, BB), 256>>>(attn, x, gamma, out);
}

// round 3
// speedup vs baseline: 2.1949x; 1.0175x over previous
#include <cuda_runtime.h>
#include <cstdint>

// Problem shapes (fixed by the dataset)
#define BB 4
#define CC 256
#define CO 32
#define NN 4096   // H*W = 64*64

// Scratch (allocation-free rule: __device__ globals)
__device__ float g_q[BB * CO * NN];                 // 2 MB
__device__ float g_k[BB * CO * NN];                 // 2 MB
__device__ float g_v[(size_t)BB * CC * NN];         // 16 MB
__device__ float g_pmax[(size_t)BB * 32 * NN];      // per-(b, mtile, n) tile max
__device__ float g_psum[(size_t)BB * 32 * NN];      // per-(b, mtile, n) tile sumexp
__device__ float g_rmax[BB * NN];                   // per-row max
__device__ float g_rinv[BB * NN];                   // per-row 1/sum

// ---------------------------------------------------------------------------
// helpers
// ---------------------------------------------------------------------------
__device__ __forceinline__ void mma_tf32_16x8x8(
    float c[4], const uint32_t a[4], const uint32_t b[2])
{
    asm volatile(
        "mma.sync.aligned.m16n8k8.row.col.f32.tf32.tf32.f32 "
        "{%0,%1,%2,%3}, {%4,%5,%6,%7}, {%8,%9}, {%0,%1,%2,%3};"
        : "+f"(c[0]), "+f"(c[1]), "+f"(c[2]), "+f"(c[3])
        : "r"(a[0]), "r"(a[1]), "r"(a[2]), "r"(a[3]),
          "r"(b[0]), "r"(b[1]));
}

__device__ __forceinline__ void cp_async16(uint32_t smem_dst, const void* gsrc) {
    asm volatile("cp.async.ca.shared.global [%0], [%1], 16;\n"
                 :: "r"(smem_dst), "l"(gsrc));
}
__device__ __forceinline__ void cp_commit() {
    asm volatile("cp.async.commit_group;\n" ::: "memory");
}
template <int N>
__device__ __forceinline__ void cp_wait() {
    asm volatile("cp.async.wait_group %0;\n" :: "n"(N) : "memory");
}

// ---------------------------------------------------------------------------
// Kernel 1: q/k projection.
// ---------------------------------------------------------------------------
__global__ __launch_bounds__(256) void qk_proj(
    const float* __restrict__ x,
    const float* __restrict__ Wq, const float* __restrict__ bq,
    const float* __restrict__ Wk, const float* __restrict__ bk)
{
    const int b  = blockIdx.y;
    const int n0 = blockIdx.x * 128;

    __shared__ float xs[32][128];
    __shared__ float wqs[32][32];
    __shared__ float wks[32][32];

    const int tid = threadIdx.x;
    const int nl  = tid & 127;
    const int oh  = tid >> 7;

    float accq[16], acck[16];
    #pragma unroll
    for (int r = 0; r < 16; r++) { accq[r] = 0.f; acck[r] = 0.f; }

    const float* xb = x + (size_t)b * CC * NN;

    for (int c0 = 0; c0 < CC; c0 += 32) {
        for (int i = tid; i < 32 * 128; i += 256) {
            int cc = i >> 7, nn = i & 127;
            xs[cc][nn] = xb[(size_t)(c0 + cc) * NN + n0 + nn];
        }
        for (int i = tid; i < 32 * 32; i += 256) {
            int o = i >> 5, cc = i & 31;
            wqs[cc][o] = Wq[o * CC + c0 + cc];
            wks[cc][o] = Wk[o * CC + c0 + cc];
        }
        __syncthreads();
        #pragma unroll
        for (int kk = 0; kk < 32; kk++) {
            float xv = xs[kk][nl];
            #pragma unroll
            for (int r = 0; r < 16; r++) {
                accq[r] += wqs[kk][oh * 16 + r] * xv;
                acck[r] += wks[kk][oh * 16 + r] * xv;
            }
        }
        __syncthreads();
    }
    #pragma unroll
    for (int r = 0; r < 16; r++) {
        int o = oh * 16 + r;
        g_q[((size_t)b * CO + o) * NN + n0 + nl] = accq[r] + bq[o];
        g_k[((size_t)b * CO + o) * NN + n0 + nl] = acck[r] + bk[o];
    }
}

// ---------------------------------------------------------------------------
// Kernel 2: v projection (fp32 SIMT).
// ---------------------------------------------------------------------------
__global__ __launch_bounds__(256) void v_proj(
    const float* __restrict__ x,
    const float* __restrict__ Wv, const float* __restrict__ bv)
{
    const int b  = blockIdx.z;
    const int c0 = blockIdx.y * 128;
    const int n0 = blockIdx.x * 128;

    __shared__ float As[16][128];
    __shared__ float Bs[16][128];

    const int tid = threadIdx.x;
    const int tx = tid & 15, ty = tid >> 4;

    float acc[8][8];
    #pragma unroll
    for (int r = 0; r < 8; r++)
        #pragma unroll
        for (int s = 0; s < 8; s++) acc[r][s] = 0.f;

    const float* xb = x + (size_t)b * CC * NN;

    for (int k0 = 0; k0 < CC; k0 += 16) {
        #pragma unroll
        for (int it = 0; it < 2; it++) {
            int idx = tid + it * 256;
            int row = idx >> 2;
            int c4  = (idx & 3) * 4;
            float4 v4 = *reinterpret_cast<const float4*>(&Wv[(c0 + row) * CC + k0 + c4]);
            As[c4 + 0][row] = v4.x; As[c4 + 1][row] = v4.y;
            As[c4 + 2][row] = v4.z; As[c4 + 3][row] = v4.w;
        }
        #pragma unroll
        for (int it = 0; it < 2; it++) {
            int idx  = tid + it * 256;
            int krow = idx >> 5;
            int nc4  = (idx & 31) * 4;
            *reinterpret_cast<float4*>(&Bs[krow][nc4]) =
                *reinterpret_cast<const float4*>(&xb[(size_t)(k0 + krow) * NN + n0 + nc4]);
        }
        __syncthreads();
        #pragma unroll
        for (int kk = 0; kk < 16; kk++) {
            float4 a0 = *reinterpret_cast<const float4*>(&As[kk][ty * 8]);
            float4 a1 = *reinterpret_cast<const float4*>(&As[kk][ty * 8 + 4]);
            float4 b0 = *reinterpret_cast<const float4*>(&Bs[kk][tx * 8]);
            float4 b1 = *reinterpret_cast<const float4*>(&Bs[kk][tx * 8 + 4]);
            float ra[8] = {a0.x, a0.y, a0.z, a0.w, a1.x, a1.y, a1.z, a1.w};
            float rb[8] = {b0.x, b0.y, b0.z, b0.w, b1.x, b1.y, b1.z, b1.w};
            #pragma unroll
            for (int r = 0; r < 8; r++)
                #pragma unroll
                for (int s = 0; s < 8; s++) acc[r][s] += ra[r] * rb[s];
        }
        __syncthreads();
    }

    #pragma unroll
    for (int r = 0; r < 8; r++) {
        int c = c0 + ty * 8 + r;
        float bias = bv[c];
        #pragma unroll
        for (int s = 0; s < 8; s += 4) {
            float4 o;
            o.x = acc[r][s + 0] + bias; o.y = acc[r][s + 1] + bias;
            o.z = acc[r][s + 2] + bias; o.w = acc[r][s + 3] + bias;
            *reinterpret_cast<float4*>(&g_v[((size_t)b * CC + c) * NN + n0 + tx * 8 + s]) = o;
        }
    }
}

// ---------------------------------------------------------------------------
// Kernel 3: raw scores (fp32 SIMT) + fused per-tile softmax statistics.
// attn[b,n,m] raw; partial max / sumexp per (b, mtile, n) written to globals.
// ---------------------------------------------------------------------------
__global__ __launch_bounds__(256) void scores_stats(float* __restrict__ attn)
{
    const int b  = blockIdx.z;
    const int m0 = blockIdx.x * 128;
    const int n0 = blockIdx.y * 128;

    __shared__ float ks[CO][128];
    __shared__ float qs[CO][128];

    const int tid = threadIdx.x;
    const float* kb = g_k + (size_t)b * CO * NN;
    const float* qb = g_q + (size_t)b * CO * NN;

    #pragma unroll
    for (int it = 0; it < 4; it++) {
        int idx = tid + it * 256;
        int row = idx >> 5;
        int c4  = (idx & 31) * 4;
        *reinterpret_cast<float4*>(&ks[row][c4]) =
            *reinterpret_cast<const float4*>(&kb[(size_t)row * NN + n0 + c4]);
        *reinterpret_cast<float4*>(&qs[row][c4]) =
            *reinterpret_cast<const float4*>(&qb[(size_t)row * NN + m0 + c4]);
    }
    __syncthreads();

    const int tx = tid & 15, ty = tid >> 4;
    float acc[8][8];
    #pragma unroll
    for (int r = 0; r < 8; r++)
        #pragma unroll
        for (int s = 0; s < 8; s++) acc[r][s] = 0.f;

    #pragma unroll
    for (int c = 0; c < CO; c++) {
        float4 a0 = *reinterpret_cast<const float4*>(&ks[c][ty * 8]);
        float4 a1 = *reinterpret_cast<const float4*>(&ks[c][ty * 8 + 4]);
        float4 b0 = *reinterpret_cast<const float4*>(&qs[c][tx * 8]);
        float4 b1 = *reinterpret_cast<const float4*>(&qs[c][tx * 8 + 4]);
        float ra[8] = {a0.x, a0.y, a0.z, a0.w, a1.x, a1.y, a1.z, a1.w};
        float rb[8] = {b0.x, b0.y, b0.z, b0.w, b1.x, b1.y, b1.z, b1.w};
        #pragma unroll
        for (int r = 0; r < 8; r++)
            #pragma unroll
            for (int s = 0; s < 8; s++) acc[r][s] += ra[r] * rb[s];
    }

    // ---- fused stats: rows n0+ty*8+r are owned by the 16 threads with this ty
    // (tx = low 4 bits of lane id -> shfl_xor over 1,2,4,8 reduces across tx).
    float rowmax[8], rowsum[8];
    #pragma unroll
    for (int r = 0; r < 8; r++) {
        float m = acc[r][0];
        #pragma unroll
        for (int s = 1; s < 8; s++) m = fmaxf(m, acc[r][s]);
        #pragma unroll
        for (int o = 8; o; o >>= 1) m = fmaxf(m, __shfl_xor_sync(0xffffffffu, m, o));
        rowmax[r] = m;
        float sm = 0.f;
        #pragma unroll
        for (int s = 0; s < 8; s++) sm += __expf(acc[r][s] - m);
        #pragma unroll
        for (int o = 8; o; o >>= 1) sm += __shfl_xor_sync(0xffffffffu, sm, o);
        rowsum[r] = sm;
    }
    if (tx == 0) {
        const int mt = blockIdx.x;           // m-tile index 0..31
        size_t base = (((size_t)b * 32 + mt) << 12) + n0 + ty * 8;
        #pragma unroll
        for (int r = 0; r < 8; r++) {
            g_pmax[base + r] = rowmax[r];
            g_psum[base + r] = rowsum[r];
        }
    }

    // ---- write raw scores
    float* ap = attn + (size_t)b * NN * NN;
    #pragma unroll
    for (int r = 0; r < 8; r++) {
        size_t n = (size_t)(n0 + ty * 8 + r);
        #pragma unroll
        for (int s = 0; s < 8; s += 4) {
            float4 o;
            o.x = acc[r][s + 0]; o.y = acc[r][s + 1];
            o.z = acc[r][s + 2]; o.w = acc[r][s + 3];
            *reinterpret_cast<float4*>(&ap[n * NN + m0 + tx * 8 + s]) = o;
        }
    }
}

// ---------------------------------------------------------------------------
// Kernel 4: combine the 32 per-tile stats per row -> rmax, 1/sum (LSE merge).
// ---------------------------------------------------------------------------
__global__ __launch_bounds__(128) void stats_reduce()
{
    const int b = blockIdx.y;
    const int n = blockIdx.x * 128 + threadIdx.x;

    float m = -1e30f;
    #pragma unroll
    for (int mt = 0; mt < 32; mt++)
        m = fmaxf(m, g_pmax[(((size_t)b * 32 + mt) << 12) + n]);

    float s = 0.f;
    #pragma unroll
    for (int mt = 0; mt < 32; mt++) {
        size_t idx = (((size_t)b * 32 + mt) << 12) + n;
        s += g_psum[idx] * __expf(g_pmax[idx] - m);
    }
    g_rmax[b * NN + n] = m;
    g_rinv[b * NN + n] = 1.0f / s;
}

// ---------------------------------------------------------------------------
// Kernel 5: streaming normalize, in place.  One block per row, no smem,
// no block-wide syncs: pure read-exp-scale-write.
// ---------------------------------------------------------------------------
__global__ __launch_bounds__(256) void normalize_rows(float* __restrict__ attn)
{
    const size_t row = blockIdx.x;          // b*NN + n
    const float rmax = g_rmax[row];
    const float rinv = g_rinv[row];
    float4* p = reinterpret_cast<float4*>(attn + row * NN);

    #pragma unroll
    for (int j = 0; j < 4; j++) {
        int i = threadIdx.x + j * 256;      // 1024 float4 per row
        float4 v = p[i];
        v.x = __expf(v.x - rmax) * rinv;
        v.y = __expf(v.y - rmax) * rinv;
        v.z = __expf(v.z - rmax) * rinv;
        v.w = __expf(v.w - rmax) * rinv;
        p[i] = v;
    }
}

// ---------------------------------------------------------------------------
// Kernel 6: out[b,c,m] = gamma * sum_n v[b,c,n]*attn[b,n,m] + x
// tf32 mma, cp.async double-buffered, raw fp32 bits fed to mma (RZ trunc).
// Block tile 128(c) x 128(m), BK=32.  Dynamic smem (~70 KB).
// ---------------------------------------------------------------------------
#define AS_PITCH 36
#define BS_PITCH 132
#define AS_STAGE (128 * AS_PITCH)
#define BS_STAGE (32 * BS_PITCH)
#define SMEM_OUT ((2 * AS_STAGE + 2 * BS_STAGE) * sizeof(float))

__global__ __launch_bounds__(256) void out_gemm_tf32(
    const float* __restrict__ attn,
    const float* __restrict__ x,
    const float* __restrict__ gamma,
    float* __restrict__ out)
{
    extern __shared__ float smem[];
    float* As = smem;                        // [2][128][36]
    float* Bs = smem + 2 * AS_STAGE;         // [2][32][132]

    const int b  = blockIdx.z;
    const int c0 = blockIdx.y * 128;
    const int m0 = blockIdx.x * 128;

    const float* vb = g_v + (size_t)b * CC * NN;
    const float* ab = attn + (size_t)b * NN * NN;

    const int tid  = threadIdx.x;
    const int lane = tid & 31;
    const int w    = tid >> 5;
    const int wc   = w >> 2;
    const int wm   = w & 3;

    const uint32_t as_base = (uint32_t)__cvta_generic_to_shared(As);
    const uint32_t bs_base = (uint32_t)__cvta_generic_to_shared(Bs);

    // per-thread cp.async slots (4 A-chunks + 4 B-chunks per stage)
    const int a_row = tid >> 1;              // 0..127 (2 threads per row)
    const int a_c4  = (tid & 1) * 16;        // float offset 0 / 16
    const int b_kr  = tid >> 3;              // 0..31  (8 threads per row)
    const int b_m4  = (tid & 7) * 16;        // float offset 0..112

    auto load_stage = [&](int s, int k0) {
        // A: v tile 128 x 32 (row = c, contiguous in k)
        const float* ga = &vb[(size_t)(c0 + a_row) * NN + k0 + a_c4];
        uint32_t da = as_base + (s * AS_STAGE + a_row * AS_PITCH + a_c4) * 4;
        cp_async16(da,      ga);
        cp_async16(da + 16, ga + 4);
        cp_async16(da + 32, ga + 8);
        cp_async16(da + 48, ga + 12);
        // B: attn tile 32 x 128 (row = k, contiguous in m)
        const float* gb = &ab[(size_t)(k0 + b_kr) * NN + m0 + b_m4];
        uint32_t db = bs_base + (s * BS_STAGE + b_kr * BS_PITCH + b_m4) * 4;
        cp_async16(db,      gb);
        cp_async16(db + 16, gb + 4);
        cp_async16(db + 32, gb + 8);
        cp_async16(db + 48, gb + 12);
    };

    float acc[4][4][4];
    #pragma unroll
    for (int mi = 0; mi < 4; mi++)
        #pragma unroll
        for (int ni = 0; ni < 4; ni++)
            #pragma unroll
            for (int r = 0; r < 4; r++) acc[mi][ni][r] = 0.f;

    const int lq = lane >> 2;
    const int lr = lane & 3;

    load_stage(0, 0);
    cp_commit();

    for (int it = 0; it < NN / 32; it++) {
        const int s = it & 1;
        if (it + 1 < NN / 32) {
            load_stage(s ^ 1, (it + 1) * 32);
            cp_commit();
            cp_wait<1>();
        } else {
            cp_wait<0>();
        }
        __syncthreads();

        const float* Asl = As + s * AS_STAGE;
        const float* Bsl = Bs + s * BS_STAGE;

        #pragma unroll
        for (int kk = 0; kk < 32; kk += 8) {
            uint32_t af[4][4];
            #pragma unroll
            for (int mi = 0; mi < 4; mi++) {
                int r = wc * 64 + mi * 16 + lq;
                af[mi][0] = __float_as_uint(Asl[(r    ) * AS_PITCH + kk + lr    ]);
                af[mi][1] = __float_as_uint(Asl[(r + 8) * AS_PITCH + kk + lr    ]);
                af[mi][2] = __float_as_uint(Asl[(r    ) * AS_PITCH + kk + lr + 4]);
                af[mi][3] = __float_as_uint(Asl[(r + 8) * AS_PITCH + kk + lr + 4]);
            }
            uint32_t bf[4][2];
            #pragma unroll
            for (int ni = 0; ni < 4; ni++) {
                int m = wm * 32 + ni * 8 + lq;
                bf[ni][0] = __float_as_uint(Bsl[(kk + lr    ) * BS_PITCH + m]);
                bf[ni][1] = __float_as_uint(Bsl[(kk + lr + 4) * BS_PITCH + m]);
            }
            #pragma unroll
            for (int mi = 0; mi < 4; mi++)
                #pragma unroll
                for (int ni = 0; ni < 4; ni++)
                    mma_tf32_16x8x8(acc[mi][ni], af[mi], bf[ni]);
        }
        __syncthreads();
    }

    const float g = __ldg(gamma);
    const float* xb = x + (size_t)b * CC * NN;
    float* ob = out + (size_t)b * CC * NN;

    #pragma unroll
    for (int mi = 0; mi < 4; mi++) {
        #pragma unroll
        for (int ni = 0; ni < 4; ni++) {
            int c = c0 + wc * 64 + mi * 16 + lq;
            int m = m0 + wm * 32 + ni * 8 + lr * 2;
            {
                size_t off = (size_t)c * NN + m;
                float2 xr = *reinterpret_cast<const float2*>(&xb[off]);
                float2 o;
                o.x = g * acc[mi][ni][0] + xr.x;
                o.y = g * acc[mi][ni][1] + xr.y;
                *reinterpret_cast<float2*>(&ob[off]) = o;
            }
            {
                size_t off = (size_t)(c + 8) * NN + m;
                float2 xr = *reinterpret_cast<const float2*>(&xb[off]);
                float2 o;
                o.x = g * acc[mi][ni][2] + xr.x;
                o.y = g * acc[mi][ni][3] + xr.y;
                *reinterpret_cast<float2*>(&ob[off]) = o;
            }
        }
    }
}

// ---------------------------------------------------------------------------
extern "C" void kernel_launch(void* const* d_in, const int* in_sizes, int n_in,
                              void* d_out, int out_size)
{
    (void)in_sizes; (void)n_in; (void)out_size;

    const float* x     = (const float*)d_in[0];
    const float* Wq    = (const float*)d_in[1];
    const float* bq    = (const float*)d_in[2];
    const float* Wk    = (const float*)d_in[3];
    const float* bk    = (const float*)d_in[4];
    const float* Wv    = (const float*)d_in[5];
    const float* bv    = (const float*)d_in[6];
    const float* gamma = (const float*)d_in[7];

    float* out  = (float*)d_out;                       // (B, C, H, W)
    float* attn = out + (size_t)BB * CC * NN;          // (B, N, N)

    static bool attr_set = false;
    if (!attr_set) {
        cudaFuncSetAttribute(out_gemm_tf32,
            cudaFuncAttributeMaxDynamicSharedMemorySize, (int)SMEM_OUT);
        attr_set = true;
    }

    qk_proj      <<<dim3(NN / 128, BB), 256>>>(x, Wq, bq, Wk, bk);
    v_proj       <<<dim3(NN / 128, CC / 128, BB), 256>>>(x, Wv, bv);
    scores_stats <<<dim3(NN / 128, NN / 128, BB), 256>>>(attn);
    stats_reduce <<<dim3(NN / 128, BB), 128>>>();
    normalize_rows<<<BB * NN, 256>>>(attn);
    out_gemm_tf32<<<dim3(NN / 128, CC / 128, BB), 256, SMEM_OUT>>>(attn, x, gamma, out);
}